// round 6
// baseline (speedup 1.0000x reference)
#include <cuda_runtime.h>
#include <cuda_bf16.h>
#include <cstdint>

#define NT    2048
#define DIM   512
#define SEG   8000
#define SEGP  8192
#define RANKS 4
#define KSPL  8     // k-splits in pass 2 (K=1024 each)

// ---------------- scratch (device globals; no allocs allowed) ----------------
__device__ int g_cnt[RANKS];
__device__ int g_list[RANKS][NT];
__device__ __align__(128) __nv_bfloat16 g_qh[NT * DIM];                     // q*invT bf16
__device__ __align__(128) __nv_bfloat16 g_embh[(size_t)RANKS * SEGP * DIM]; // [r][v][d], padded
__device__ __align__(128) __nv_bfloat16 g_P[(size_t)NT * SEGP];             // exp(scores)
__device__ float g_lpart[NT][64];                                           // row-sum partials
__device__ float g_ctxp[KSPL][NT][DIM];                                     // ctx partials

// ---------------- helpers ----------------
__device__ __forceinline__ uint32_t smem_u32(const void* p) {
    uint32_t a;
    asm("{ .reg .u64 t; cvta.to.shared.u64 t, %1; cvt.u32.u64 %0, t; }" : "=r"(a) : "l"(p));
    return a;
}
__device__ __forceinline__ void cpa16(uint32_t d, const void* s) {
    asm volatile("cp.async.cg.shared.global [%0], [%1], 16;" :: "r"(d), "l"(s));
}
#define CPA_COMMIT() asm volatile("cp.async.commit_group;" ::: "memory")
#define CPA_WAIT(n)  asm volatile("cp.async.wait_group %0;" :: "n"(n) : "memory")

__device__ __forceinline__ void ldsm4(uint32_t f[4], uint32_t a) {
    asm volatile("ldmatrix.sync.aligned.m8n8.x4.shared.b16 {%0,%1,%2,%3}, [%4];"
        : "=r"(f[0]), "=r"(f[1]), "=r"(f[2]), "=r"(f[3]) : "r"(a));
}
__device__ __forceinline__ void ldsm4t(uint32_t f[4], uint32_t a) {
    asm volatile("ldmatrix.sync.aligned.m8n8.x4.trans.shared.b16 {%0,%1,%2,%3}, [%4];"
        : "=r"(f[0]), "=r"(f[1]), "=r"(f[2]), "=r"(f[3]) : "r"(a));
}
__device__ __forceinline__ void mma16816(float c[4], const uint32_t a[4], const uint32_t* b) {
    asm volatile("mma.sync.aligned.m16n8k16.row.col.f32.bf16.bf16.f32 "
        "{%0,%1,%2,%3}, {%4,%5,%6,%7}, {%8,%9}, {%0,%1,%2,%3};"
        : "+f"(c[0]), "+f"(c[1]), "+f"(c[2]), "+f"(c[3])
        : "r"(a[0]), "r"(a[1]), "r"(a[2]), "r"(a[3]), "r"(b[0]), "r"(b[1]));
}

// ---------------- small kernels ----------------
__global__ void k_build(const int* __restrict__ xr) {
    if (threadIdx.x < RANKS) g_cnt[threadIdx.x] = 0;
    __syncthreads();
    for (int i = threadIdx.x; i < NT; i += 256) {
        int r = xr[i];
        int p = atomicAdd(&g_cnt[r], 1);
        g_list[r][p] = i;
    }
}

__global__ void k_prep_q(const float* __restrict__ q) {
    int i = blockIdx.x * 256 + threadIdx.x;
    const float inv = 0.04419417382415922f;   // 1/sqrt(512)
    float4 a = *reinterpret_cast<const float4*>(q + (size_t)i * 8);
    float4 b = *reinterpret_cast<const float4*>(q + (size_t)i * 8 + 4);
    __nv_bfloat16 h[8];
    h[0] = __float2bfloat16(a.x * inv); h[1] = __float2bfloat16(a.y * inv);
    h[2] = __float2bfloat16(a.z * inv); h[3] = __float2bfloat16(a.w * inv);
    h[4] = __float2bfloat16(b.x * inv); h[5] = __float2bfloat16(b.y * inv);
    h[6] = __float2bfloat16(b.z * inv); h[7] = __float2bfloat16(b.w * inv);
    *reinterpret_cast<uint4*>(g_qh + (size_t)i * 8) = *reinterpret_cast<uint4*>(h);
}

__global__ void k_prep_emb(const float* __restrict__ emb) {
    int i = blockIdx.x * 256 + threadIdx.x;
    int d8 = i & 63;
    int vv = i >> 6;
    int r = vv >> 13, v = vv & 8191;
    __nv_bfloat16 h[8];
    if (v < SEG) {
        const float* s = emb + ((size_t)r * SEG + v) * DIM + d8 * 8;
        float4 a = *reinterpret_cast<const float4*>(s);
        float4 b = *reinterpret_cast<const float4*>(s + 4);
        h[0] = __float2bfloat16(a.x); h[1] = __float2bfloat16(a.y);
        h[2] = __float2bfloat16(a.z); h[3] = __float2bfloat16(a.w);
        h[4] = __float2bfloat16(b.x); h[5] = __float2bfloat16(b.y);
        h[6] = __float2bfloat16(b.z); h[7] = __float2bfloat16(b.w);
    } else {
        #pragma unroll
        for (int m = 0; m < 8; ++m) h[m] = __float2bfloat16(0.f);
    }
    *reinterpret_cast<uint4*>(g_embh + (size_t)vv * DIM + d8 * 8) = *reinterpret_cast<uint4*>(h);
}

// ---------------- pass 1: P = exp(Q.E^T), row-sum partials ----------------
// C tile 128 tok x 128 vocab, K=512 in 8 chunks of 64, 3-stage pipeline.
// grid (16 token tiles, 4 ranks, 64 vsplits); 256 thr; smem 96KB
__device__ __forceinline__ void k1_load(uint32_t smb, int stage, const int* toks,
                                        const __nv_bfloat16* esrc, int kc0, int tid) {
    uint32_t pd = smb + stage * 32768, ed = pd + 16384;
    #pragma unroll
    for (int j = 0; j < 4; ++j) {                       // A=Q: 128 rows x 8 chunks
        int i = tid + j * 256; int rr = i >> 3, cc = i & 7;
        cpa16(pd + rr * 128 + ((cc ^ (rr & 7)) << 4),
              g_qh + (size_t)toks[rr] * DIM + kc0 + cc * 8);
    }
    #pragma unroll
    for (int j = 0; j < 4; ++j) {                       // B=E: 128 rows x 8 chunks
        int i = tid + j * 256; int rr = i >> 3, cc = i & 7;
        cpa16(ed + rr * 128 + ((cc ^ (rr & 7)) << 4),
              esrc + (size_t)rr * DIM + kc0 + cc * 8);
    }
}

__global__ void __launch_bounds__(256)
k_scores() {
    int r = blockIdx.y;
    int cnt = g_cnt[r];
    int t0 = blockIdx.x * 128;
    if (t0 >= cnt) return;
    int vs = blockIdx.z;

    extern __shared__ char sm[];
    __shared__ int   toks[128];
    __shared__ float rs[2][128];

    const int tid = threadIdx.x, lane = tid & 31, wid = tid >> 5;
    const int mg = wid >> 1, ng = wid & 1;

    for (int i = tid; i < 128; i += 256) toks[i] = g_list[r][min(t0 + i, cnt - 1)];
    __syncthreads();

    const uint32_t smb = smem_u32(sm);
    const __nv_bfloat16* esrc = g_embh + ((size_t)r * SEGP + (size_t)vs * 128) * DIM;

    const int la7 = lane & 7;
    const int aRow0 = mg * 32 + la7 + ((lane >> 3) & 1) * 8;     // +mi*16
    const int aChB  = lane >> 4;
    const int bRow4 = ng * 64 + ((lane >> 4) << 3) + la7;        // +ni*8 (ni even)
    const int bChB4 = (lane >> 3) & 1;
    const int epiV  = (lane & 3) * 2;

    float c[2][8][4];
    #pragma unroll
    for (int mi = 0; mi < 2; ++mi)
        #pragma unroll
        for (int ni = 0; ni < 8; ++ni)
            #pragma unroll
            for (int j = 0; j < 4; ++j) c[mi][ni][j] = 0.f;

    k1_load(smb, 0, toks, esrc, 0, tid);
    CPA_COMMIT();
    k1_load(smb, 1, toks, esrc, 64, tid);
    CPA_COMMIT();

    int stage = 0;
    for (int ch = 0; ch < 8; ++ch) {
        if (ch < 7) { CPA_WAIT(1); } else { CPA_WAIT(0); }
        __syncthreads();
        if (ch < 6) {
            int st = stage + 2; if (st >= 3) st -= 3;
            k1_load(smb, st, toks, esrc, (ch + 2) * 64, tid);
            CPA_COMMIT();
        }

        uint32_t pb = smb + stage * 32768;
        uint32_t eb = pb + 16384;
        #pragma unroll
        for (int ks = 0; ks < 4; ++ks) {
            uint32_t a0[4], a1[4];
            uint32_t aswz = (uint32_t)(((ks * 2 + aChB) ^ la7) << 4);
            ldsm4(a0, pb + aRow0 * 128 + aswz);
            ldsm4(a1, pb + (aRow0 + 16) * 128 + aswz);
            uint32_t bswz = (uint32_t)(((ks * 2 + bChB4) ^ la7) << 4);
            #pragma unroll
            for (int ni = 0; ni < 8; ni += 2) {
                uint32_t bb[4];
                ldsm4(bb, eb + (bRow4 + ni * 8) * 128 + bswz);
                mma16816(c[0][ni],     a0, bb);
                mma16816(c[1][ni],     a1, bb);
                mma16816(c[0][ni + 1], a0, bb + 2);
                mma16816(c[1][ni + 1], a1, bb + 2);
            }
        }
        if (++stage == 3) stage = 0;
    }

    // epilogue: exp, P->global (bf16), row sums (once per CTA)
    #pragma unroll
    for (int mi = 0; mi < 2; ++mi) {
        int rowlo = mg * 32 + mi * 16 + (lane >> 2);
        int rowhi = rowlo + 8;
        int toklo = toks[rowlo], tokhi = toks[rowhi];
        float slo = 0.f, shi = 0.f;
        #pragma unroll
        for (int ni = 0; ni < 8; ++ni) {
            int v = vs * 128 + ng * 64 + ni * 8 + epiV;
            float p0 = (v     < SEG) ? __expf(c[mi][ni][0]) : 0.f;
            float p1 = (v + 1 < SEG) ? __expf(c[mi][ni][1]) : 0.f;
            float p2 = (v     < SEG) ? __expf(c[mi][ni][2]) : 0.f;
            float p3 = (v + 1 < SEG) ? __expf(c[mi][ni][3]) : 0.f;
            slo += p0 + p1; shi += p2 + p3;
            __nv_bfloat162 h0 = __floats2bfloat162_rn(p0, p1);
            __nv_bfloat162 h1 = __floats2bfloat162_rn(p2, p3);
            *reinterpret_cast<uint32_t*>(g_P + (size_t)toklo * SEGP + v) =
                *reinterpret_cast<uint32_t*>(&h0);
            *reinterpret_cast<uint32_t*>(g_P + (size_t)tokhi * SEGP + v) =
                *reinterpret_cast<uint32_t*>(&h1);
        }
        slo += __shfl_xor_sync(0xffffffffu, slo, 1);
        slo += __shfl_xor_sync(0xffffffffu, slo, 2);
        shi += __shfl_xor_sync(0xffffffffu, shi, 1);
        shi += __shfl_xor_sync(0xffffffffu, shi, 2);
        if ((lane & 3) == 0) { rs[ng][rowlo] = slo; rs[ng][rowhi] = shi; }
    }
    __syncthreads();
    for (int i = tid; i < 128; i += 256)
        g_lpart[toks[i]][vs] = rs[0][i] + rs[1][i];
}

// ---------------- pass 2: ctx partials = P.E over a K slice ----------------
// C tile 128 tok x 128 dim, K=1024 per CTA in 16 chunks of 64, 3-stage pipeline.
// grid (16 tiles, 4 ranks, 8 ksplits * 4 dsplits); 256 thr; smem 96KB
__device__ __forceinline__ void k2_load(uint32_t smb, int stage, const int* toks,
                                        int rank, int ns, int kc0, int tid) {
    uint32_t pd = smb + stage * 32768, ed = pd + 16384;
    #pragma unroll
    for (int j = 0; j < 4; ++j) {                       // A=P: 128 rows x 8 chunks
        int i = tid + j * 256; int rr = i >> 3, cc = i & 7;
        cpa16(pd + rr * 128 + ((cc ^ (rr & 7)) << 4),
              g_P + (size_t)toks[rr] * SEGP + kc0 + cc * 8);
    }
    #pragma unroll
    for (int j = 0; j < 4; ++j) {                       // B=E: 64 rows x 16 chunks
        int i = tid + j * 256; int rr = i >> 4, cc = i & 15;
        cpa16(ed + rr * 256 + ((cc ^ (rr & 7)) << 4),
              g_embh + ((size_t)rank * SEGP + kc0 + rr) * DIM + (size_t)ns * 128 + cc * 8);
    }
}

__global__ void __launch_bounds__(256)
k_ctx() {
    int r = blockIdx.y;
    int cnt = g_cnt[r];
    int t0 = blockIdx.x * 128;
    if (t0 >= cnt) return;
    int kz = blockIdx.z >> 2;       // 0..7
    int ns = blockIdx.z & 3;        // 0..3

    extern __shared__ char sm[];
    __shared__ int toks[128];

    const int tid = threadIdx.x, lane = tid & 31, wid = tid >> 5;
    const int mg = wid >> 1, ng = wid & 1;

    for (int i = tid; i < 128; i += 256) toks[i] = g_list[r][min(t0 + i, cnt - 1)];
    __syncthreads();

    const uint32_t smb = smem_u32(sm);

    const int la7 = lane & 7;
    const int aRow0 = mg * 32 + la7 + ((lane >> 3) & 1) * 8;
    const int aChB  = lane >> 4;
    const int bKr4  = la7 + ((lane >> 3) & 1) * 8;     // +ks*16
    const int bCh4  = lane >> 4;                       // + n-chunk base

    float c[2][8][4];
    #pragma unroll
    for (int mi = 0; mi < 2; ++mi)
        #pragma unroll
        for (int ni = 0; ni < 8; ++ni)
            #pragma unroll
            for (int j = 0; j < 4; ++j) c[mi][ni][j] = 0.f;

    const int kbase = kz * 1024;
    k2_load(smb, 0, toks, r, ns, kbase, tid);
    CPA_COMMIT();
    k2_load(smb, 1, toks, r, ns, kbase + 64, tid);
    CPA_COMMIT();

    int stage = 0;
    for (int ch = 0; ch < 16; ++ch) {
        if (ch < 15) { CPA_WAIT(1); } else { CPA_WAIT(0); }
        __syncthreads();
        if (ch < 14) {
            int st = stage + 2; if (st >= 3) st -= 3;
            k2_load(smb, st, toks, r, ns, kbase + (ch + 2) * 64, tid);
            CPA_COMMIT();
        }

        uint32_t pb = smb + stage * 32768;
        uint32_t eb = pb + 16384;
        #pragma unroll
        for (int ks = 0; ks < 4; ++ks) {
            uint32_t a0[4], a1[4];
            uint32_t aswz = (uint32_t)(((ks * 2 + aChB) ^ la7) << 4);
            ldsm4(a0, pb + aRow0 * 128 + aswz);
            ldsm4(a1, pb + (aRow0 + 16) * 128 + aswz);
            int krow = ks * 16 + bKr4;
            #pragma unroll
            for (int ni = 0; ni < 8; ni += 2) {
                uint32_t bb[4];
                ldsm4t(bb, eb + krow * 256 + ((((ng * 8 + ni) + bCh4) ^ la7) << 4));
                mma16816(c[0][ni],     a0, bb);
                mma16816(c[1][ni],     a1, bb);
                mma16816(c[0][ni + 1], a0, bb + 2);
                mma16816(c[1][ni + 1], a1, bb + 2);
            }
        }
        if (++stage == 3) stage = 0;
    }

    // epilogue: raw partials to g_ctxp[kz]
    #pragma unroll
    for (int mi = 0; mi < 2; ++mi) {
        int rowlo = mg * 32 + mi * 16 + (lane >> 2);
        int rowhi = rowlo + 8;
        int toklo = toks[rowlo], tokhi = toks[rowhi];
        #pragma unroll
        for (int ni = 0; ni < 8; ++ni) {
            int col = ns * 128 + ng * 64 + ni * 8 + (lane & 3) * 2;
            float2 wa, wb;
            wa.x = c[mi][ni][0]; wa.y = c[mi][ni][1];
            wb.x = c[mi][ni][2]; wb.y = c[mi][ni][3];
            *reinterpret_cast<float2*>(&g_ctxp[kz][toklo][col]) = wa;
            *reinterpret_cast<float2*>(&g_ctxp[kz][tokhi][col]) = wb;
        }
    }
}

// ---------------- final: out = (sum_ks ctxp)/l + q ----------------
__global__ void k_final(const float* __restrict__ qg, float* __restrict__ out) {
    int tok = blockIdx.x;
    int lane = threadIdx.x;   // 32
    float l = g_lpart[tok][lane] + g_lpart[tok][lane + 32];
    #pragma unroll
    for (int o = 16; o; o >>= 1) l += __shfl_xor_sync(0xffffffffu, l, o);
    float linv = 1.f / l;
    #pragma unroll
    for (int j = 0; j < 4; ++j) {
        int d = (j * 32 + lane) * 4;
        float4 s = *reinterpret_cast<const float4*>(&g_ctxp[0][tok][d]);
        #pragma unroll
        for (int k = 1; k < KSPL; ++k) {
            float4 t = *reinterpret_cast<const float4*>(&g_ctxp[k][tok][d]);
            s.x += t.x; s.y += t.y; s.z += t.z; s.w += t.w;
        }
        float4 qv = *reinterpret_cast<const float4*>(qg + (size_t)tok * DIM + d);
        float4 o4;
        o4.x = s.x * linv + qv.x; o4.y = s.y * linv + qv.y;
        o4.z = s.z * linv + qv.z; o4.w = s.w * linv + qv.w;
        *reinterpret_cast<float4*>(out + (size_t)tok * DIM + d) = o4;
    }
}

// ---------------- launch ----------------
extern "C" void kernel_launch(void* const* d_in, const int* in_sizes, int n_in,
                              void* d_out, int out_size) {
    const float* q   = (const float*)d_in[0];
    const int*   xr  = (const int*)  d_in[1];
    const float* emb = (const float*)d_in[2];
    float*       out = (float*)d_out;

    cudaFuncSetAttribute((const void*)k_scores,
                         cudaFuncAttributeMaxDynamicSharedMemorySize, 98304);
    cudaFuncSetAttribute((const void*)k_ctx,
                         cudaFuncAttributeMaxDynamicSharedMemorySize, 98304);

    k_build<<<1, 256>>>(xr);
    k_prep_q<<<512, 256>>>(q);
    k_prep_emb<<<8192, 256>>>(emb);

    dim3 g1(16, 4, 64);
    k_scores<<<g1, 256, 98304>>>();
    dim3 g2(16, 4, 32);
    k_ctx<<<g2, 256, 98304>>>();
    k_final<<<NT, 32>>>(q, out);
}

// round 7
// speedup vs baseline: 1.0874x; 1.0874x over previous
#include <cuda_runtime.h>
#include <cuda_bf16.h>
#include <cstdint>

#define NT    2048
#define DIM   512
#define SEG   8000
#define SEGP  8192
#define RANKS 4
#define KSPL  8     // k-splits in pass 2 (K=1024 each)

// ---------------- scratch (device globals; no allocs allowed) ----------------
__device__ int g_cnt[RANKS];
__device__ int g_list[RANKS][NT];
__device__ __align__(128) __nv_bfloat16 g_qh[NT * DIM];                     // q*invT bf16
__device__ __align__(128) __nv_bfloat16 g_embh[(size_t)RANKS * SEGP * DIM]; // [r][v][d], padded
__device__ __align__(128) __nv_bfloat16 g_P[(size_t)NT * SEGP];             // exp(scores)
__device__ float g_lpart[NT][64];                                           // row-sum partials
__device__ float g_ctxp[KSPL][NT][DIM];                                     // ctx partials

// ---------------- helpers ----------------
__device__ __forceinline__ uint32_t smem_u32(const void* p) {
    uint32_t a;
    asm("{ .reg .u64 t; cvta.to.shared.u64 t, %1; cvt.u32.u64 %0, t; }" : "=r"(a) : "l"(p));
    return a;
}
__device__ __forceinline__ void cpa16(uint32_t d, const void* s) {
    asm volatile("cp.async.cg.shared.global [%0], [%1], 16;" :: "r"(d), "l"(s));
}
#define CPA_COMMIT() asm volatile("cp.async.commit_group;" ::: "memory")
#define CPA_WAIT(n)  asm volatile("cp.async.wait_group %0;" :: "n"(n) : "memory")

__device__ __forceinline__ void ldsm4(uint32_t f[4], uint32_t a) {
    asm volatile("ldmatrix.sync.aligned.m8n8.x4.shared.b16 {%0,%1,%2,%3}, [%4];"
        : "=r"(f[0]), "=r"(f[1]), "=r"(f[2]), "=r"(f[3]) : "r"(a));
}
__device__ __forceinline__ void ldsm4t(uint32_t f[4], uint32_t a) {
    asm volatile("ldmatrix.sync.aligned.m8n8.x4.trans.shared.b16 {%0,%1,%2,%3}, [%4];"
        : "=r"(f[0]), "=r"(f[1]), "=r"(f[2]), "=r"(f[3]) : "r"(a));
}
__device__ __forceinline__ void mma16816(float c[4], const uint32_t a[4], const uint32_t* b) {
    asm volatile("mma.sync.aligned.m16n8k16.row.col.f32.bf16.bf16.f32 "
        "{%0,%1,%2,%3}, {%4,%5,%6,%7}, {%8,%9}, {%0,%1,%2,%3};"
        : "+f"(c[0]), "+f"(c[1]), "+f"(c[2]), "+f"(c[3])
        : "r"(a[0]), "r"(a[1]), "r"(a[2]), "r"(a[3]), "r"(b[0]), "r"(b[1]));
}

// ---------------- small kernels ----------------
__global__ void k_build(const int* __restrict__ xr) {
    if (threadIdx.x < RANKS) g_cnt[threadIdx.x] = 0;
    __syncthreads();
    for (int i = threadIdx.x; i < NT; i += 256) {
        int r = xr[i];
        int p = atomicAdd(&g_cnt[r], 1);
        g_list[r][p] = i;
    }
}

__global__ void k_prep_q(const float* __restrict__ q) {
    int i = blockIdx.x * 256 + threadIdx.x;
    const float inv = 0.04419417382415922f;   // 1/sqrt(512)
    float4 a = *reinterpret_cast<const float4*>(q + (size_t)i * 8);
    float4 b = *reinterpret_cast<const float4*>(q + (size_t)i * 8 + 4);
    __nv_bfloat16 h[8];
    h[0] = __float2bfloat16(a.x * inv); h[1] = __float2bfloat16(a.y * inv);
    h[2] = __float2bfloat16(a.z * inv); h[3] = __float2bfloat16(a.w * inv);
    h[4] = __float2bfloat16(b.x * inv); h[5] = __float2bfloat16(b.y * inv);
    h[6] = __float2bfloat16(b.z * inv); h[7] = __float2bfloat16(b.w * inv);
    *reinterpret_cast<uint4*>(g_qh + (size_t)i * 8) = *reinterpret_cast<uint4*>(h);
}

__global__ void k_prep_emb(const float* __restrict__ emb) {
    int i = blockIdx.x * 256 + threadIdx.x;
    int d8 = i & 63;
    int vv = i >> 6;
    int r = vv >> 13, v = vv & 8191;
    __nv_bfloat16 h[8];
    if (v < SEG) {
        const float* s = emb + ((size_t)r * SEG + v) * DIM + d8 * 8;
        float4 a = *reinterpret_cast<const float4*>(s);
        float4 b = *reinterpret_cast<const float4*>(s + 4);
        h[0] = __float2bfloat16(a.x); h[1] = __float2bfloat16(a.y);
        h[2] = __float2bfloat16(a.z); h[3] = __float2bfloat16(a.w);
        h[4] = __float2bfloat16(b.x); h[5] = __float2bfloat16(b.y);
        h[6] = __float2bfloat16(b.z); h[7] = __float2bfloat16(b.w);
    } else {
        #pragma unroll
        for (int m = 0; m < 8; ++m) h[m] = __float2bfloat16(0.f);
    }
    *reinterpret_cast<uint4*>(g_embh + (size_t)vv * DIM + d8 * 8) = *reinterpret_cast<uint4*>(h);
}

// ---------------- pass 1: P = exp(Q.E^T), row-sum partials ----------------
// C tile 128 tok x 128 vocab, 4 warps (64x64 each), K=512 in 8 chunks, 3-stage.
// grid (16 token tiles, 4 ranks, 64 vsplits); 128 thr; smem 96KB
__device__ __forceinline__ void k1_load(uint32_t smb, int stage, const int* toks,
                                        const __nv_bfloat16* esrc, int kc0, int tid) {
    uint32_t pd = smb + stage * 32768, ed = pd + 16384;
    #pragma unroll
    for (int j = 0; j < 8; ++j) {                       // A=Q: 128 rows x 8 chunks
        int i = tid + j * 128; int rr = i >> 3, cc = i & 7;
        cpa16(pd + rr * 128 + ((cc ^ (rr & 7)) << 4),
              g_qh + (size_t)toks[rr] * DIM + kc0 + cc * 8);
    }
    #pragma unroll
    for (int j = 0; j < 8; ++j) {                       // B=E: 128 rows x 8 chunks
        int i = tid + j * 128; int rr = i >> 3, cc = i & 7;
        cpa16(ed + rr * 128 + ((cc ^ (rr & 7)) << 4),
              esrc + (size_t)rr * DIM + kc0 + cc * 8);
    }
}

__global__ void __launch_bounds__(128, 2)
k_scores() {
    int r = blockIdx.y;
    int cnt = g_cnt[r];
    int t0 = blockIdx.x * 128;
    if (t0 >= cnt) return;
    int vs = blockIdx.z;

    extern __shared__ char sm[];
    __shared__ int   toks[128];
    __shared__ float rs[2][128];

    const int tid = threadIdx.x, lane = tid & 31, wid = tid >> 5;
    const int mg = wid >> 1, ng = wid & 1;     // 2x2 warps, 64x64 tiles

    toks[tid] = g_list[r][min(t0 + tid, cnt - 1)];
    __syncthreads();

    const uint32_t smb = smem_u32(sm);
    const __nv_bfloat16* esrc = g_embh + ((size_t)r * SEGP + (size_t)vs * 128) * DIM;

    const int la7 = lane & 7;
    const int aRow0 = mg * 64 + la7 + ((lane >> 3) & 1) * 8;     // +mi*16
    const int aChB  = lane >> 4;
    const int bRow4 = ng * 64 + ((lane >> 4) << 3) + la7;        // +ni*8 (ni even)
    const int bChB4 = (lane >> 3) & 1;
    const int epiV  = (lane & 3) * 2;

    float c[4][8][4];
    #pragma unroll
    for (int mi = 0; mi < 4; ++mi)
        #pragma unroll
        for (int ni = 0; ni < 8; ++ni)
            #pragma unroll
            for (int j = 0; j < 4; ++j) c[mi][ni][j] = 0.f;

    k1_load(smb, 0, toks, esrc, 0, tid);
    CPA_COMMIT();
    k1_load(smb, 1, toks, esrc, 64, tid);
    CPA_COMMIT();

    int stage = 0;
    for (int ch = 0; ch < 8; ++ch) {
        if (ch < 7) { CPA_WAIT(1); } else { CPA_WAIT(0); }
        __syncthreads();
        if (ch < 6) {
            int st = stage + 2; if (st >= 3) st -= 3;
            k1_load(smb, st, toks, esrc, (ch + 2) * 64, tid);
            CPA_COMMIT();
        }

        uint32_t pb = smb + stage * 32768;
        uint32_t eb = pb + 16384;
        #pragma unroll
        for (int ks = 0; ks < 4; ++ks) {
            uint32_t a[4][4];
            uint32_t aswz = (uint32_t)(((ks * 2 + aChB) ^ la7) << 4);
            #pragma unroll
            for (int mi = 0; mi < 4; ++mi)
                ldsm4(a[mi], pb + (aRow0 + mi * 16) * 128 + aswz);
            uint32_t bswz = (uint32_t)(((ks * 2 + bChB4) ^ la7) << 4);
            #pragma unroll
            for (int ni = 0; ni < 8; ni += 2) {
                uint32_t bb[4];
                ldsm4(bb, eb + (bRow4 + ni * 8) * 128 + bswz);
                #pragma unroll
                for (int mi = 0; mi < 4; ++mi) {
                    mma16816(c[mi][ni],     a[mi], bb);
                    mma16816(c[mi][ni + 1], a[mi], bb + 2);
                }
            }
        }
        if (++stage == 3) stage = 0;
    }

    // epilogue: exp, P->global (bf16), row sums (once per CTA)
    #pragma unroll
    for (int mi = 0; mi < 4; ++mi) {
        int rowlo = mg * 64 + mi * 16 + (lane >> 2);
        int rowhi = rowlo + 8;
        int toklo = toks[rowlo], tokhi = toks[rowhi];
        float slo = 0.f, shi = 0.f;
        #pragma unroll
        for (int ni = 0; ni < 8; ++ni) {
            int v = vs * 128 + ng * 64 + ni * 8 + epiV;
            float p0 = (v     < SEG) ? __expf(c[mi][ni][0]) : 0.f;
            float p1 = (v + 1 < SEG) ? __expf(c[mi][ni][1]) : 0.f;
            float p2 = (v     < SEG) ? __expf(c[mi][ni][2]) : 0.f;
            float p3 = (v + 1 < SEG) ? __expf(c[mi][ni][3]) : 0.f;
            slo += p0 + p1; shi += p2 + p3;
            __nv_bfloat162 h0 = __floats2bfloat162_rn(p0, p1);
            __nv_bfloat162 h1 = __floats2bfloat162_rn(p2, p3);
            *reinterpret_cast<uint32_t*>(g_P + (size_t)toklo * SEGP + v) =
                *reinterpret_cast<uint32_t*>(&h0);
            *reinterpret_cast<uint32_t*>(g_P + (size_t)tokhi * SEGP + v) =
                *reinterpret_cast<uint32_t*>(&h1);
        }
        slo += __shfl_xor_sync(0xffffffffu, slo, 1);
        slo += __shfl_xor_sync(0xffffffffu, slo, 2);
        shi += __shfl_xor_sync(0xffffffffu, shi, 1);
        shi += __shfl_xor_sync(0xffffffffu, shi, 2);
        if ((lane & 3) == 0) { rs[ng][rowlo] = slo; rs[ng][rowhi] = shi; }
    }
    __syncthreads();
    g_lpart[toks[tid]][vs] = rs[0][tid] + rs[1][tid];
}

// ---------------- pass 2: ctx partials = P.E over a K slice ----------------
// C tile 128 tok x 128 dim, 4 warps (64x64), K=1024 in 16 chunks, 3-stage.
// grid (16 tiles, 4 ranks, 8 ksplits * 4 dsplits); 128 thr; smem 96KB
__device__ __forceinline__ void k2_load(uint32_t smb, int stage, const int* toks,
                                        int rank, int ns, int kc0, int tid) {
    uint32_t pd = smb + stage * 32768, ed = pd + 16384;
    #pragma unroll
    for (int j = 0; j < 8; ++j) {                       // A=P: 128 rows x 8 chunks
        int i = tid + j * 128; int rr = i >> 3, cc = i & 7;
        cpa16(pd + rr * 128 + ((cc ^ (rr & 7)) << 4),
              g_P + (size_t)toks[rr] * SEGP + kc0 + cc * 8);
    }
    #pragma unroll
    for (int j = 0; j < 8; ++j) {                       // B=E: 64 rows x 16 chunks
        int i = tid + j * 128; int rr = i >> 4, cc = i & 15;
        cpa16(ed + rr * 256 + ((cc ^ (rr & 7)) << 4),
              g_embh + ((size_t)rank * SEGP + kc0 + rr) * DIM + (size_t)ns * 128 + cc * 8);
    }
}

__global__ void __launch_bounds__(128, 2)
k_ctx() {
    int r = blockIdx.y;
    int cnt = g_cnt[r];
    int t0 = blockIdx.x * 128;
    if (t0 >= cnt) return;
    int kz = blockIdx.z >> 2;       // 0..7
    int ns = blockIdx.z & 3;        // 0..3

    extern __shared__ char sm[];
    __shared__ int toks[128];

    const int tid = threadIdx.x, lane = tid & 31, wid = tid >> 5;
    const int mg = wid >> 1, ng = wid & 1;

    toks[tid] = g_list[r][min(t0 + tid, cnt - 1)];
    __syncthreads();

    const uint32_t smb = smem_u32(sm);

    const int la7 = lane & 7;
    const int aRow0 = mg * 64 + la7 + ((lane >> 3) & 1) * 8;
    const int aChB  = lane >> 4;
    const int bKr4  = la7 + ((lane >> 3) & 1) * 8;     // +ks*16
    const int bCh4  = lane >> 4;                       // + n-chunk base

    float c[4][8][4];
    #pragma unroll
    for (int mi = 0; mi < 4; ++mi)
        #pragma unroll
        for (int ni = 0; ni < 8; ++ni)
            #pragma unroll
            for (int j = 0; j < 4; ++j) c[mi][ni][j] = 0.f;

    const int kbase = kz * 1024;
    k2_load(smb, 0, toks, r, ns, kbase, tid);
    CPA_COMMIT();
    k2_load(smb, 1, toks, r, ns, kbase + 64, tid);
    CPA_COMMIT();

    int stage = 0;
    for (int ch = 0; ch < 16; ++ch) {
        if (ch < 15) { CPA_WAIT(1); } else { CPA_WAIT(0); }
        __syncthreads();
        if (ch < 14) {
            int st = stage + 2; if (st >= 3) st -= 3;
            k2_load(smb, st, toks, r, ns, kbase + (ch + 2) * 64, tid);
            CPA_COMMIT();
        }

        uint32_t pb = smb + stage * 32768;
        uint32_t eb = pb + 16384;
        #pragma unroll
        for (int ks = 0; ks < 4; ++ks) {
            uint32_t a[4][4];
            uint32_t aswz = (uint32_t)(((ks * 2 + aChB) ^ la7) << 4);
            #pragma unroll
            for (int mi = 0; mi < 4; ++mi)
                ldsm4(a[mi], pb + (aRow0 + mi * 16) * 128 + aswz);
            int krow = ks * 16 + bKr4;
            #pragma unroll
            for (int ni = 0; ni < 8; ni += 2) {
                uint32_t bb[4];
                ldsm4t(bb, eb + krow * 256 + ((((ng * 8 + ni) + bCh4) ^ la7) << 4));
                #pragma unroll
                for (int mi = 0; mi < 4; ++mi) {
                    mma16816(c[mi][ni],     a[mi], bb);
                    mma16816(c[mi][ni + 1], a[mi], bb + 2);
                }
            }
        }
        if (++stage == 3) stage = 0;
    }

    // epilogue: raw partials to g_ctxp[kz]
    #pragma unroll
    for (int mi = 0; mi < 4; ++mi) {
        int rowlo = mg * 64 + mi * 16 + (lane >> 2);
        int rowhi = rowlo + 8;
        int toklo = toks[rowlo], tokhi = toks[rowhi];
        #pragma unroll
        for (int ni = 0; ni < 8; ++ni) {
            int col = ns * 128 + ng * 64 + ni * 8 + (lane & 3) * 2;
            float2 wa, wb;
            wa.x = c[mi][ni][0]; wa.y = c[mi][ni][1];
            wb.x = c[mi][ni][2]; wb.y = c[mi][ni][3];
            *reinterpret_cast<float2*>(&g_ctxp[kz][toklo][col]) = wa;
            *reinterpret_cast<float2*>(&g_ctxp[kz][tokhi][col]) = wb;
        }
    }
}

// ---------------- final: out = (sum_ks ctxp)/l + q ----------------
__global__ void k_final(const float* __restrict__ qg, float* __restrict__ out) {
    int tok = blockIdx.x;
    int lane = threadIdx.x;   // 32
    float l = g_lpart[tok][lane] + g_lpart[tok][lane + 32];
    #pragma unroll
    for (int o = 16; o; o >>= 1) l += __shfl_xor_sync(0xffffffffu, l, o);
    float linv = 1.f / l;
    #pragma unroll
    for (int j = 0; j < 4; ++j) {
        int d = (j * 32 + lane) * 4;
        float4 s = *reinterpret_cast<const float4*>(&g_ctxp[0][tok][d]);
        #pragma unroll
        for (int k = 1; k < KSPL; ++k) {
            float4 t = *reinterpret_cast<const float4*>(&g_ctxp[k][tok][d]);
            s.x += t.x; s.y += t.y; s.z += t.z; s.w += t.w;
        }
        float4 qv = *reinterpret_cast<const float4*>(qg + (size_t)tok * DIM + d);
        float4 o4;
        o4.x = s.x * linv + qv.x; o4.y = s.y * linv + qv.y;
        o4.z = s.z * linv + qv.z; o4.w = s.w * linv + qv.w;
        *reinterpret_cast<float4*>(out + (size_t)tok * DIM + d) = o4;
    }
}

// ---------------- launch ----------------
extern "C" void kernel_launch(void* const* d_in, const int* in_sizes, int n_in,
                              void* d_out, int out_size) {
    const float* q   = (const float*)d_in[0];
    const int*   xr  = (const int*)  d_in[1];
    const float* emb = (const float*)d_in[2];
    float*       out = (float*)d_out;

    cudaFuncSetAttribute((const void*)k_scores,
                         cudaFuncAttributeMaxDynamicSharedMemorySize, 98304);
    cudaFuncSetAttribute((const void*)k_ctx,
                         cudaFuncAttributeMaxDynamicSharedMemorySize, 98304);

    k_build<<<1, 256>>>(xr);
    k_prep_q<<<512, 256>>>(q);
    k_prep_emb<<<8192, 256>>>(emb);

    dim3 g1(16, 4, 64);
    k_scores<<<g1, 128, 98304>>>();
    dim3 g2(16, 4, 32);
    k_ctx<<<g2, 128, 98304>>>();
    k_final<<<NT, 32>>>(q, out);
}